// round 11
// baseline (speedup 1.0000x reference)
#include <cuda_runtime.h>

// x_seq (T=16, N=8, C=64, H=64, W=64) fp32; conv_weight (64,64,3,3) fp32.
// z = conv3x3(pad=1) via Winograd F(2x2,3x3), then LIF scan over T.
#define T_  16
#define NB  8
#define C_  64
#define H_  64
#define W_  64
#define B_  (T_ * NB)
#define HW_ (H_ * W_)
#define CHW (C_ * HW_)
#define INNER (NB * CHW)        // 2097152 per timestep

// Scratch (static device globals — no allocation).
__device__ float g_z[(size_t)B_ * CHW];
__device__ float g_U[16 * 64 * 64];     // transformed weights U[pos][ci][co]

typedef unsigned long long u64;

__device__ __forceinline__ void fma2(u64& a, u64 x, u64 w) {
    asm("fma.rn.f32x2 %0, %1, %2, %3;" : "=l"(a) : "l"(x), "l"(w), "l"(a));
}
__device__ __forceinline__ void add2(u64& a, u64 b) {
    asm("add.rn.f32x2 %0, %1, %2;" : "=l"(a) : "l"(a), "l"(b));
}
__device__ __forceinline__ u64 dup2(float v) {
    u64 r; asm("mov.b64 %0, {%1, %1};" : "=l"(r) : "f"(v)); return r;
}

__device__ __forceinline__ void cpa4(unsigned saddr, const float* g) {
    asm volatile("cp.async.ca.shared.global [%0], [%1], 4;"
                 :: "r"(saddr), "l"(g) : "memory");
}
__device__ __forceinline__ void cpa16(unsigned saddr, const float* g) {
    asm volatile("cp.async.ca.shared.global [%0], [%1], 16;"
                 :: "r"(saddr), "l"(g) : "memory");
}
#define CP_COMMIT() asm volatile("cp.async.commit_group;" ::: "memory")
#define CP_WAIT0()  asm volatile("cp.async.wait_group 0;" ::: "memory")

// ---------------------------------------------------------------------------
// Weight transform: U = G g G^T per (co, ci). G = [[1,0,0],[.5,.5,.5],
// [.5,-.5,.5],[0,0,1]] (exact power-of-two coefficients).
// Layout g_U[pos][ci][co], pos = 4*i + j.
// ---------------------------------------------------------------------------
__global__ void wtrans_kernel(const float* __restrict__ w) {
    int idx = blockIdx.x * 256 + threadIdx.x;   // 0..4095
    int co = idx >> 6, ci = idx & 63;
    const float* g = w + ((size_t)co * 64 + ci) * 9;
    float g0[3] = {g[0], g[1], g[2]};
    float g1[3] = {g[3], g[4], g[5]};
    float g2[3] = {g[6], g[7], g[8]};
    float t[4][3];
#pragma unroll
    for (int j = 0; j < 3; j++) {
        t[0][j] = g0[j];
        t[1][j] = 0.5f * (g0[j] + g1[j] + g2[j]);
        t[2][j] = 0.5f * (g0[j] - g1[j] + g2[j]);
        t[3][j] = g2[j];
    }
#pragma unroll
    for (int i = 0; i < 4; i++) {
        float u0 = t[i][0];
        float u1 = 0.5f * (t[i][0] + t[i][1] + t[i][2]);
        float u2 = 0.5f * (t[i][0] - t[i][1] + t[i][2]);
        float u3 = t[i][2];
        g_U[(4 * i + 0) * 4096 + ci * 64 + co] = u0;
        g_U[(4 * i + 1) * 4096 + ci * 64 + co] = u1;
        g_U[(4 * i + 2) * 4096 + ci * 64 + co] = u2;
        g_U[(4 * i + 3) * 4096 + ci * 64 + co] = u3;
    }
}

// ---------------------------------------------------------------------------
// Winograd F(2x2,3x3) conv. Block = image x 8x8 output region (16 wtiles)
// x 32 couts. 16 cp.async double-buffered chunks of 4 cin:
//   V = B^T d B in smem -> 16 pos-GEMMs (thread = (pos, wtile), m[32 co]
//   as 16 FFMA2 accs, folded into totals every 16 ci) -> smem exchange ->
//   out = A^T m A -> g_z.
// smem layout (floats): XIN [0,960) | VS [960,3008) | UW [3008,7104);
// exchange overlays [960, ...).
// ---------------------------------------------------------------------------
#define XIN_OFF 0
#define VS_OFF  960
#define UW_OFF  3008
#define EX_OFF  960
#define SMF     7104

__global__ __launch_bounds__(256, 2)
void wino_kernel(const float* __restrict__ x) {
    __shared__ __align__(16) float sm[SMF];

    const int gy = blockIdx.x >> 3, gx = blockIdx.x & 7;   // 8x8 region grid
    const int b  = blockIdx.y;                              // image
    const int cog = blockIdx.z;                             // co group (32)
    const int R0 = gy * 8, C0 = gx * 8;
    const int tid = threadIdx.x;

    // ---- staging precompute: input slots (480 = 4ci x 10r x 12c padded) ----
    int xrel[2];
    unsigned vmask = 0;
#pragma unroll
    for (int s = 0; s < 2; s++) {
        int idx = tid + 256 * s;
        int ci = idx / 120;
        int rem = idx - ci * 120;
        int r = rem / 12, c = rem - r * 12;
        int gh = R0 - 1 + r, gw = C0 - 1 + c;
        bool valid = (idx < 480) && (c < 10) &&
                     ((unsigned)gh < (unsigned)H_) &&
                     ((unsigned)gw < (unsigned)W_);
        xrel[s] = ci * HW_ + gh * W_ + gw;
        if (valid) vmask |= (1u << s);
    }
    const float* xb = x + (size_t)b * CHW;
    const unsigned smb = (unsigned)__cvta_generic_to_shared(sm);

    // ---- zero both xin buffers (halo slots never rewritten) ----
    for (int i = tid; i < 960; i += 256) sm[XIN_OFF + i] = 0.0f;
    __syncthreads();

    // ---- prefetch chunk 0 ----
    {
#pragma unroll
        for (int s = 0; s < 2; s++)
            if (vmask & (1u << s))
                cpa4(smb + (unsigned)(XIN_OFF + tid + 256 * s) * 4u, xb + xrel[s]);
#pragma unroll
        for (int s = 0; s < 2; s++) {
            int g = tid + 256 * s;                 // 0..511 vec4 groups
            int pos = g >> 5, r = g & 31;
            int ci_l = r >> 3, co4 = r & 7;
            const float* gp = &g_U[pos * 4096 + ci_l * 64 + cog * 32 + co4 * 4];
            cpa16(smb + (unsigned)(UW_OFF + g * 4) * 4u, gp);
        }
        CP_COMMIT();
    }

    u64 m[16], tot[16];
#pragma unroll
    for (int j = 0; j < 16; j++) { m[j] = 0ULL; tot[j] = 0ULL; }

#pragma unroll 1
    for (int ch = 0; ch < 16; ch++) {
        const int buf = ch & 1;
        CP_WAIT0();
        __syncthreads();

        // ---- V = B^T d B : thread = (ci, i-row, wtile) ----
        {
            int ci = tid >> 6;            // 0..3
            int i  = (tid >> 4) & 3;      // transform row 0..3
            int wt = tid & 15;
            int wy = wt >> 2, wx = wt & 3;
            // t row i: rows of d: i0:(0,2,-) i1:(1,2,+) i2:(2,1,-) i3:(1,3,-)
            int rA = (i == 3) ? 1 : i;
            int rB = (i <= 1) ? 2 : ((i == 2) ? 1 : 3);
            float sgn = (i == 1) ? 1.0f : -1.0f;
            const float* dbase = &sm[XIN_OFF + buf * 480 + ci * 120 +
                                     (2 * wy) * 12 + 2 * wx];
            float t0 = __fmaf_rn(sgn, dbase[rB * 12 + 0], dbase[rA * 12 + 0]);
            float t1 = __fmaf_rn(sgn, dbase[rB * 12 + 1], dbase[rA * 12 + 1]);
            float t2 = __fmaf_rn(sgn, dbase[rB * 12 + 2], dbase[rA * 12 + 2]);
            float t3 = __fmaf_rn(sgn, dbase[rB * 12 + 3], dbase[rA * 12 + 3]);
            float* vs = &sm[VS_OFF + buf * 1024 + ci * 16 + wt];
            vs[(4 * i + 0) * 64] = t0 - t2;
            vs[(4 * i + 1) * 64] = t1 + t2;
            vs[(4 * i + 2) * 64] = t2 - t1;
            vs[(4 * i + 3) * 64] = t1 - t3;
        }
        __syncthreads();

        // ---- prefetch next chunk into other buffer ----
        if (ch < 15) {
            const float* xp = xb + (ch + 1) * 4 * HW_;
            const int nb = buf ^ 1;
#pragma unroll
            for (int s = 0; s < 2; s++)
                if (vmask & (1u << s))
                    cpa4(smb + (unsigned)(XIN_OFF + nb * 480 + tid + 256 * s) * 4u,
                         xp + xrel[s]);
#pragma unroll
            for (int s = 0; s < 2; s++) {
                int g = tid + 256 * s;
                int pos = g >> 5, r = g & 31;
                int ci_l = r >> 3, co4 = r & 7;
                const float* gp = &g_U[pos * 4096 + ((ch + 1) * 4 + ci_l) * 64 +
                                       cog * 32 + co4 * 4];
                cpa16(smb + (unsigned)(UW_OFF + nb * 2048 + g * 4) * 4u, gp);
            }
            CP_COMMIT();
        }

        // ---- pos-GEMM: thread = (pos, wtile); m[32 co] += U * V ----
        {
            int pos = tid >> 4, wt = tid & 15;
#pragma unroll
            for (int ci = 0; ci < 4; ci++) {
                u64 v = dup2(sm[VS_OFF + buf * 1024 + (pos * 4 + ci) * 16 + wt]);
                const ulonglong2* uq = (const ulonglong2*)
                    &sm[UW_OFF + buf * 2048 + (pos * 4 + ci) * 32];
#pragma unroll
                for (int q = 0; q < 8; q++) {
                    ulonglong2 u = uq[q];
                    fma2(m[2 * q + 0], v, u.x);
                    fma2(m[2 * q + 1], v, u.y);
                }
            }
        }
        // fold every 4 chunks (16 ci) into totals — two-level summation
        if ((ch & 3) == 3) {
#pragma unroll
            for (int j = 0; j < 16; j++) { add2(tot[j], m[j]); m[j] = 0ULL; }
        }
    }
    __syncthreads();

    // ---- exchange + output transform (2 co-chunks of 16) ----
    const int wy = tid >> 6, co_l = (tid >> 2) & 15, wx = tid & 3;
    const int pos_w = tid >> 4, wt_w = tid & 15;
#pragma unroll 1
    for (int c = 0; c < 2; c++) {
        // write this thread's 8 co-pairs for chunk c
#pragma unroll
        for (int j2 = 0; j2 < 8; j2++) {
            *reinterpret_cast<u64*>(
                &sm[EX_OFF + wt_w * 290 + pos_w * 18 + 2 * j2]) = tot[8 * c + j2];
        }
        __syncthreads();
        // read 16 pos for site (wy, wx, co_l); out = A^T m A
        float mm[16];
        {
            int base = EX_OFF + (wy * 4 + wx) * 290 + co_l;
#pragma unroll
            for (int p = 0; p < 16; p++) mm[p] = sm[base + p * 18];
        }
        float t0[4], t1[4];
#pragma unroll
        for (int j = 0; j < 4; j++) {
            t0[j] = mm[0 + j] + mm[4 + j] + mm[8 + j];
            t1[j] = mm[4 + j] - mm[8 + j] - mm[12 + j];
        }
        float o00 = t0[0] + t0[1] + t0[2];
        float o01 = t0[1] - t0[2] - t0[3];
        float o10 = t1[0] + t1[1] + t1[2];
        float o11 = t1[1] - t1[2] - t1[3];
        int co_g = cog * 32 + c * 16 + co_l;
        size_t ob = (size_t)b * CHW + (size_t)co_g * HW_ +
                    (size_t)(R0 + 2 * wy) * W_ + (C0 + 2 * wx);
        *(float2*)&g_z[ob]       = make_float2(o00, o01);
        *(float2*)&g_z[ob + W_]  = make_float2(o10, o11);
        __syncthreads();
    }
}

// ---------------------------------------------------------------------------
// LIF scan over T, float4-vectorized: v += (x - v)/2 ; spike=(v>=1); reset 0.
// ---------------------------------------------------------------------------
__global__ __launch_bounds__(256)
void lif_kernel(float* __restrict__ out) {
    int i = blockIdx.x * blockDim.x + threadIdx.x;   // float4 index
    const float4* z4 = (const float4*)g_z;
    float4* o4 = (float4*)out;
    float4 v = make_float4(0.f, 0.f, 0.f, 0.f);
#pragma unroll
    for (int t = 0; t < T_; t++) {
        float4 xv = z4[(size_t)t * (INNER / 4) + i];
        v.x = v.x + (xv.x - v.x) * 0.5f;
        v.y = v.y + (xv.y - v.y) * 0.5f;
        v.z = v.z + (xv.z - v.z) * 0.5f;
        v.w = v.w + (xv.w - v.w) * 0.5f;
        float4 s;
        s.x = (v.x >= 1.0f) ? 1.0f : 0.0f;
        s.y = (v.y >= 1.0f) ? 1.0f : 0.0f;
        s.z = (v.z >= 1.0f) ? 1.0f : 0.0f;
        s.w = (v.w >= 1.0f) ? 1.0f : 0.0f;
        o4[(size_t)t * (INNER / 4) + i] = s;
        if (v.x >= 1.0f) v.x = 0.0f;
        if (v.y >= 1.0f) v.y = 0.0f;
        if (v.z >= 1.0f) v.z = 0.0f;
        if (v.w >= 1.0f) v.w = 0.0f;
    }
}

extern "C" void kernel_launch(void* const* d_in, const int* in_sizes, int n_in,
                              void* d_out, int out_size) {
    const float* x = (const float*)d_in[0];
    const float* w = (const float*)d_in[1];
    float* out = (float*)d_out;

    wtrans_kernel<<<16, 256>>>(w);                       // U = G g G^T
    dim3 grid(64, B_, 2);                                // 8x8 regions, 128 imgs, 2 co groups
    wino_kernel<<<grid, 256>>>(x);
    lif_kernel<<<(INNER / 4) / 256, 256>>>(out);
}